// round 16
// baseline (speedup 1.0000x reference)
#include <cuda_runtime.h>
#include <cuda_bf16.h>
#include <math.h>
#include <stdint.h>

#define cB 8
#define cN 128
#define cF 128
#define cTf 64
#define cTm 256
#define cDf 32
#define cDm 128
#define cE 64
#define cH 128
#define QSCALE 0.08838834764831843f

typedef unsigned long long ull;

// ---------------- device scratch ----------------
__device__ __align__(16) unsigned char g_kvB[cB*65536];     // per b: swizzled [m=256][h=128] bf16
__device__ __align__(16) unsigned char g_qA[cB*cN*16384];   // per n: swizzled [f=64][h=128] bf16 (q*scale)
__device__ float g_qt[cB*cN*cH];                            // q at t-row (fp32)
__device__ float g_h[cB*cN*cE];                             // node hidden
__device__ float g_A[cB*cN*cH];
__device__ float g_Bv[cB*cN*cH];
__device__ float g_pw[cB*16*cTf*cTm];                       // attn-weight partials per n-group

// ---------------- helpers ----------------
__device__ __forceinline__ uint32_t smem_u32(const void* p){
    uint32_t a;
    asm("{ .reg .u64 t; cvta.to.shared.u64 t, %1; cvt.u32.u64 %0, t; }" : "=r"(a) : "l"(p));
    return a;
}
__device__ __forceinline__ uint32_t tile_off(int r, int c, int atom_rows){
    uint32_t boff = (uint32_t)((r>>3) + (c>>6)*atom_rows)*1024u + (uint32_t)(r&7)*128u + (uint32_t)(c&63)*2u;
    return boff ^ ((boff >> 3) & 0x70u);
}
#define LDM_X4(r, a) \
    asm volatile("ldmatrix.sync.aligned.m8n8.x4.shared.b16 {%0,%1,%2,%3}, [%4];" \
        : "=r"((r)[0]),"=r"((r)[1]),"=r"((r)[2]),"=r"((r)[3]) : "r"(a))

__device__ __forceinline__ void mma_bf16(float* c, const uint32_t* a, uint32_t b0, uint32_t b1){
    asm volatile("mma.sync.aligned.m16n8k16.row.col.f32.bf16.bf16.f32 "
        "{%0,%1,%2,%3}, {%4,%5,%6,%7}, {%8,%9}, {%0,%1,%2,%3};"
        : "+f"(c[0]),"+f"(c[1]),"+f"(c[2]),"+f"(c[3])
        : "r"(a[0]),"r"(a[1]),"r"(a[2]),"r"(a[3]), "r"(b0),"r"(b1));
}

// fast exp on the FMA pipe
__device__ __forceinline__ float fexp(float v){
    float t = fmaf(v, 1.4426950408889634f, 12582912.0f);
    int   j = __float_as_int(t) - 0x4B400000;
    float kf = t - 12582912.0f;
    float x = fmaf(kf, -0.6931471805599453f, v);
    float p = 1.3888889e-3f;
    p = fmaf(p, x, 8.3333333e-3f);
    p = fmaf(p, x, 4.1666667e-2f);
    p = fmaf(p, x, 1.6666667e-1f);
    p = fmaf(p, x, 0.5f);
    p = fmaf(p, x, 1.0f);
    p = fmaf(p, x, 1.0f);
    return p * __int_as_float((j + 127) << 23);
}

// packed f32x2
__device__ __forceinline__ ull pack2(float x){ ull r; asm("mov.b64 %0, {%1, %1};" : "=l"(r) : "f"(x)); return r; }
__device__ __forceinline__ ull packab(float a, float b){ ull r; asm("mov.b64 %0, {%1, %2};" : "=l"(r) : "f"(a), "f"(b)); return r; }
__device__ __forceinline__ void fma2(ull &acc, ull a, ull b){ asm("fma.rn.f32x2 %0, %1, %2, %0;" : "+l"(acc) : "l"(a), "l"(b)); }
__device__ __forceinline__ float2 u2f2(ull v){ float2 f; asm("mov.b64 {%0, %1}, %2;" : "=f"(f.x), "=f"(f.y) : "l"(v)); return f; }

// ---------------- prep: kv (0..63) + node-h (64..127) + q (128..639) ----------------
__global__ void __launch_bounds__(256) prep_kernel(const float* __restrict__ music,
                                                   const float* __restrict__ W,
                                                   const float* __restrict__ bias,
                                                   const float* __restrict__ nf,
                                                   const float* __restrict__ Wn,
                                                   const float* __restrict__ bn,
                                                   const float* __restrict__ feat,
                                                   const float* __restrict__ Wq,
                                                   const float* __restrict__ bq,
                                                   const int* __restrict__ t,
                                                   float* __restrict__ out_loss){
    extern __shared__ float sm[];
    int tid = threadIdx.x;
    int bx = blockIdx.x;
    if (bx < 64){
        // kv -> bf16 swizzled tile
        float* sW = sm + 128*257;
        int b = bx >> 3, hc = bx & 7;
        for (int idx = tid; idx < cTm*cDm; idx += 256){
            int m = idx >> 7, d = idx & 127;
            sm[d*257 + m] = music[((size_t)b*cTm + m)*cDm + d];
        }
        for (int idx = tid; idx < 128*16; idx += 256){
            int d = idx >> 4, hh = idx & 15;
            sW[idx] = W[d*cH + hc*16 + hh];
        }
        __syncthreads();
        int m = tid;
        unsigned char* tb = g_kvB + (size_t)b*65536;
        for (int hh = 0; hh < 16; hh++){
            int h = hc*16 + hh;
            float acc = bias[h];
            #pragma unroll 8
            for (int d = 0; d < cDm; d++)
                acc = fmaf(sm[d*257 + m], sW[d*16 + hh], acc);
            *(__nv_bfloat16*)(tb + tile_off(m, h, 32)) = __float2bfloat16(acc);
        }
    } else if (bx < 128){
        // node hidden: 16 n per block
        int idx = bx - 64;
        int b = idx >> 3, n0 = (idx & 7) * 16;
        float* sWn = sm;             // [f=128][e=64]
        float* sNF = sm + 8192;      // [16 n][128 f]
        {
            const float4* s1 = (const float4*)Wn;
            float4* d1 = (float4*)sWn;
            for (int i = tid; i < 2048; i += 256) d1[i] = s1[i];
            const float4* s2 = (const float4*)(nf + (size_t)(b*cN + n0)*cF);
            float4* d2 = (float4*)sNF;
            for (int i = tid; i < 512; i += 256) d2[i] = s2[i];
        }
        __syncthreads();
        int e = tid & 63, nn = tid >> 6;
        float a0 = bn[e], a1 = a0, a2 = a0, a3 = a0;
        const float* f0 = sNF + (nn*4+0)*cF;
        const float* f1 = sNF + (nn*4+1)*cF;
        const float* f2 = sNF + (nn*4+2)*cF;
        const float* f3 = sNF + (nn*4+3)*cF;
        #pragma unroll 8
        for (int f = 0; f < cF; f++){
            float w = sWn[f*cE + e];
            a0 = fmaf(f0[f], w, a0);
            a1 = fmaf(f1[f], w, a1);
            a2 = fmaf(f2[f], w, a2);
            a3 = fmaf(f3[f], w, a3);
        }
        size_t hb = (size_t)(b*cN + n0 + nn*4)*cE + e;
        g_h[hb]        = a0;
        g_h[hb + cE]   = a1;
        g_h[hb + 2*cE] = a2;
        g_h[hb + 3*cE] = a3;
    } else {
        // q: two n per block (half = tid>>7)
        int half = tid >> 7, wt = tid & 127;
        int bn_ = (bx - 128)*2 + half;
        int b = bn_ >> 7;
        float* sfeat = sm + half*2048;
        if (bx == 128 && tid == 0) *out_loss = 0.f;
        int trow = t[b]; trow = trow < 0 ? 0 : (trow > cTf-1 ? cTf-1 : trow);
        {
            const float4* fs = (const float4*)(feat + (size_t)bn_*cTf*cDf);
            float4* fd = (float4*)sfeat;
            #pragma unroll
            for (int i = wt; i < 512; i += 128) fd[i] = fs[i];
        }
        float w[cDf];
        #pragma unroll
        for (int d = 0; d < cDf; d++) w[d] = Wq[d*cH + wt];
        float bs = bq[wt];
        __syncthreads();
        unsigned char* tb = g_qA + (size_t)bn_*16384;
        for (int j = 0; j < 32; j++){
            ull acc = pack2(bs);
            const float* ra = sfeat + (2*j)*cDf;
            const float* rb = sfeat + (2*j+1)*cDf;
            #pragma unroll
            for (int d = 0; d < cDf; d++)
                fma2(acc, packab(ra[d], rb[d]), pack2(w[d]));
            float2 q2 = u2f2(acc);
            if (2*j   == trow) g_qt[(size_t)bn_*cH + wt] = q2.x;
            if (2*j+1 == trow) g_qt[(size_t)bn_*cH + wt] = q2.y;
            *(__nv_bfloat16*)(tb + tile_off(2*j,   wt, 8)) = __float2bfloat16(q2.x * QSCALE);
            *(__nv_bfloat16*)(tb + tile_off(2*j+1, wt, 8)) = __float2bfloat16(q2.y * QSCALE);
        }
    }
}

// ---------------- attention + fused ab tail ----------------
#define SM_B    0
#define SM_A    65536
#define SM_ZU   98304
#define SM_PROW 102400
#define SM_RED  110592
#define SM_HT   110848
#define SM_TES  112896
#define ATTN_SMEM 113152

__global__ void __launch_bounds__(256, 1) attn_kernel(const int* __restrict__ t,
                                                      const float* __restrict__ W1,
                                                      const float* __restrict__ b1,
                                                      float* __restrict__ out_loss){
    extern __shared__ char smem[];
    uint32_t sbase = smem_u32(smem);
    float2* zu    = (float2*)(smem + SM_ZU);    // [2][64 rows][4 wm] (dead after main loop)
    float*  cT    = (float*)(smem + SM_ZU);     // reuse: [c=128][8n]
    float*  prowS = (float*)(smem + SM_PROW);   // [8 n][256 m]
    float*  red   = (float*)(smem + SM_RED);
    float*  hT    = (float*)(smem + SM_HT);     // [e=64][8n]
    float*  tes   = (float*)(smem + SM_TES);    // 64

    int tid = threadIdx.x, wid = tid >> 5, lane = tid & 31;
    int b = blockIdx.x >> 4, grp = blockIdx.x & 15, nbase = grp * 8;
    int bn0 = b*cN + nbase;
    int wf = wid >> 2, wm = wid & 3;
    int f0 = wf*32, m0 = wm*64;
    int qr = lane >> 2, qc = lane & 3;

    {
        const float4* bs = (const float4*)(g_kvB + (size_t)b*65536);
        float4* bd = (float4*)(smem + SM_B);
        #pragma unroll
        for (int i = 0; i < 16; i++) bd[tid + i*256] = bs[tid + i*256];
        const float4* as = (const float4*)(g_qA + (size_t)bn0*16384);
        float4* ad = (float4*)(smem + SM_A);
        #pragma unroll
        for (int i = 0; i < 4; i++) ad[tid + i*256] = as[tid + i*256];
    }
    __syncthreads();

    int trow = t[b]; trow = trow < 0 ? 0 : (trow > cTf-1 ? cTf-1 : trow);
    float entacc = 0.f;
    float accW[2][8][4];
    #pragma unroll
    for (int mt = 0; mt < 2; mt++)
        #pragma unroll
        for (int nt = 0; nt < 8; nt++)
            #pragma unroll
            for (int i = 0; i < 4; i++) accW[mt][nt][i] = 0.f;

    int arow = (lane & 15), acolk = (lane >> 4) * 8;
    int brow = ((lane >> 4) & 1) * 8 + (lane & 7), bcolk = ((lane >> 3) & 1) * 8;

    for (int np = 0; np < 8; np++){
        uint32_t smA = sbase + SM_A + (np&1)*16384;
        uint32_t smB = sbase + SM_B;

        float C[2][8][4];
        #pragma unroll
        for (int mt = 0; mt < 2; mt++)
            #pragma unroll
            for (int nt = 0; nt < 8; nt++)
                #pragma unroll
                for (int i = 0; i < 4; i++) C[mt][nt][i] = 0.f;

        #pragma unroll
        for (int kk = 0; kk < 8; kk++){
            int k0 = kk*16;
            uint32_t a0[4], a1[4], bb[4][4];
            LDM_X4(a0, smA + tile_off(f0 + arow,      k0 + acolk, 8));
            LDM_X4(a1, smA + tile_off(f0 + 16 + arow, k0 + acolk, 8));
            #pragma unroll
            for (int nt2 = 0; nt2 < 4; nt2++)
                LDM_X4(bb[nt2], smB + tile_off(m0 + nt2*16 + brow, k0 + bcolk, 32));
            #pragma unroll
            for (int nt = 0; nt < 8; nt++){
                uint32_t b0 = bb[nt>>1][(nt&1)*2], b1v = bb[nt>>1][(nt&1)*2 + 1];
                mma_bf16(C[0][nt], a0, b0, b1v);
                mma_bf16(C[1][nt], a1, b0, b1v);
            }
        }

        // early LDG of next A tile
        float4 stg0, stg1, stg2, stg3;
        if (np < 7){
            const float4* as = (const float4*)(g_qA + (size_t)(bn0 + np + 1)*16384);
            stg0 = as[tid];       stg1 = as[tid + 256];
            stg2 = as[tid + 512]; stg3 = as[tid + 768];
        }

        // ---- part1: exp + Z/U + zu write ----
        #pragma unroll
        for (int g = 0; g < 4; g++){
            int mt = g >> 1, pr = g & 1;
            float Z = 0.f, U = 0.f;
            #pragma unroll
            for (int nt = 0; nt < 8; nt++){
                #pragma unroll
                for (int c = 0; c < 2; c++){
                    float v = C[mt][nt][pr*2 + c];
                    float e = fexp(v);
                    Z += e; U = fmaf(e, v, U);
                    C[mt][nt][pr*2 + c] = e;
                }
            }
            #pragma unroll
            for (int o = 1; o <= 2; o <<= 1){
                Z += __shfl_xor_sync(0xffffffffu, Z, o);
                U += __shfl_xor_sync(0xffffffffu, U, o);
            }
            if (qc == 0){
                int f = f0 + mt*16 + qr + 8*pr;
                zu[(np&1)*256 + f*4 + wm] = make_float2(Z, U);
            }
        }

        if (np < 7){
            float4* ad = (float4*)(smem + SM_A + ((np+1)&1)*16384);
            ad[tid]       = stg0; ad[tid + 256] = stg1;
            ad[tid + 512] = stg2; ad[tid + 768] = stg3;
        }
        __syncthreads();

        // ---- part2 ----
        #pragma unroll
        for (int g = 0; g < 4; g++){
            int mt = g >> 1, pr = g & 1;
            int f = f0 + mt*16 + qr + 8*pr;
            const float2* zr = zu + (np&1)*256 + f*4;
            float2 z0 = zr[0], z1 = zr[1], z2 = zr[2], z3 = zr[3];
            float Zt = z0.x + z1.x + z2.x + z3.x;
            float Ut = z0.y + z1.y + z2.y + z3.y;
            float inv = __fdividef(1.f, Zt);
            if (wm == 0 && qc == 0) entacc += __logf(Zt) - Ut*inv;
            bool isT = (f == trow);
            #pragma unroll
            for (int nt = 0; nt < 8; nt++){
                #pragma unroll
                for (int c = 0; c < 2; c++){
                    float p = C[mt][nt][pr*2 + c] * inv;
                    accW[mt][nt][pr*2 + c] += p;
                    if (isT) prowS[np*256 + m0 + nt*8 + 2*qc + c] = p;
                }
            }
        }
    }
    __syncthreads();    // zu dead from here; cT aliases it

    // ctx for the 8 t-rows -> cT[h][8n] = qt + ctx
    {
        int g = tid >> 7, h = tid & 127;
        uint32_t hbase = (uint32_t)(h >> 6)*32768u;
        uint32_t hlow  = (uint32_t)((h & 63)*2);
        uint32_t offj[8];
        #pragma unroll
        for (int j = 0; j < 8; j++) offj[j] = (uint32_t)(j*128) + (hlow ^ (uint32_t)(j<<4));
        float c0=0.f, c1=0.f, c2=0.f, c3=0.f;
        const float* pr = prowS + g*4*256;
        for (int mg = 0; mg < 32; mg++){
            uint32_t abase = hbase + (uint32_t)mg*1024u;
            #pragma unroll
            for (int j = 0; j < 8; j++){
                unsigned short u = *(const unsigned short*)(smem + SM_B + abase + offj[j]);
                float kvv = __bfloat162float(*reinterpret_cast<__nv_bfloat16*>(&u));
                int m = mg*8 + j;
                c0 = fmaf(pr[m],       kvv, c0);
                c1 = fmaf(pr[256 + m], kvv, c1);
                c2 = fmaf(pr[512 + m], kvv, c2);
                c3 = fmaf(pr[768 + m], kvv, c3);
            }
        }
        size_t qb = ((size_t)bn0 + 4*g)*cH + h;
        cT[h*8 + 4*g + 0] = g_qt[qb]        + c0;
        cT[h*8 + 4*g + 1] = g_qt[qb + cH]   + c1;
        cT[h*8 + 4*g + 2] = g_qt[qb + 2*cH] + c2;
        cT[h*8 + 4*g + 3] = g_qt[qb + 3*cH] + c3;
    }

    // stage hT [e][8n], tes
    for (int i = tid; i < 512; i += 256){
        int n = i >> 6, e = i & 63;
        hT[e*8 + n] = g_h[(size_t)(bn0 + n)*cE + e];
    }
    if (tid < 32){
        float invf = expf(-(float)tid * (logf(10000.0f) / 31.0f));
        float fr = (float)trow * invf;
        tes[tid]      = sinf(fr);
        tes[tid + 32] = cosf(fr);
    }

    #pragma unroll
    for (int o = 16; o > 0; o >>= 1) entacc += __shfl_xor_sync(0xffffffffu, entacc, o);
    if (lane == 0) red[wid] = entacc;
    __syncthreads();    // covers cT, hT, tes, red
    if (tid == 0){
        float tot = 0.f;
        #pragma unroll
        for (int i = 0; i < 8; i++) tot += red[i];
        atomicAdd(out_loss, tot * (1.f/(float)(cB*cN*cTf)));
    }

    // attn-weight partials: plain STG.64
    float* pw = g_pw + ((size_t)(b*16 + grp))*cTf*cTm;
    #pragma unroll
    for (int mt = 0; mt < 2; mt++)
        #pragma unroll
        for (int nt = 0; nt < 8; nt++)
            #pragma unroll
            for (int pr = 0; pr < 2; pr++){
                int f = f0 + mt*16 + qr + 8*pr;
                int m = m0 + nt*8 + 2*qc;
                *(float2*)(pw + f*cTm + m) =
                    make_float2(accW[mt][nt][pr*2], accW[mt][nt][pr*2 + 1]);
            }

    // ---- fused ab: thread (k = tid&127, g2 = tid>>7), 4 n each ----
    {
        int k = tid & 127, g2 = tid >> 7;
        float tw = b1[k];
        #pragma unroll 8
        for (int e = 0; e < 64; e++)
            tw = fmaf(tes[e], W1[(258 + e)*cH + k], tw);
        float a[4] = {0.f, 0.f, 0.f, 0.f};
        float bv[4] = {tw, tw, tw, tw};
        const float4* hr = (const float4*)hT + g2;
        const float4* cr = (const float4*)cT + g2;
        #pragma unroll 8
        for (int e = 0; e < 64; e++){
            float wa = W1[e*cH + k];
            float wb = W1[(64 + e)*cH + k];
            float4 h4 = hr[e*2];
            a[0]  = fmaf(h4.x, wa, a[0]);  a[1]  = fmaf(h4.y, wa, a[1]);
            a[2]  = fmaf(h4.z, wa, a[2]);  a[3]  = fmaf(h4.w, wa, a[3]);
            bv[0] = fmaf(h4.x, wb, bv[0]); bv[1] = fmaf(h4.y, wb, bv[1]);
            bv[2] = fmaf(h4.z, wb, bv[2]); bv[3] = fmaf(h4.w, wb, bv[3]);
        }
        #pragma unroll 8
        for (int c = 0; c < 128; c++){
            float wc = W1[(130 + c)*cH + k];
            float4 c4 = cr[c*2];
            bv[0] = fmaf(c4.x, wc, bv[0]); bv[1] = fmaf(c4.y, wc, bv[1]);
            bv[2] = fmaf(c4.z, wc, bv[2]); bv[3] = fmaf(c4.w, wc, bv[3]);
        }
        size_t i0 = (size_t)(bn0 + 4*g2)*cH + k;
        #pragma unroll
        for (int i = 0; i < 4; i++){
            g_A[i0 + (size_t)i*cH]  = a[i];
            g_Bv[i0 + (size_t)i*cH] = bv[i];
        }
    }
}

// ---------------- final edge MLP (k-outer) + attn-weight reduce head ----------------
#define FK_BV   0
#define FK_A8   16896
#define FK_WA   17920
#define FK_WG   18048
#define FK_W2   18176
#define FK_SMEM ((18176 + 128 + 32) * 4)

__global__ void __launch_bounds__(256) final_kernel(const float* __restrict__ adj,
                                                    const float* __restrict__ gpre,
                                                    const float* __restrict__ W1,
                                                    const float* __restrict__ W2,
                                                    const float* __restrict__ b2,
                                                    float* __restrict__ out,
                                                    float* __restrict__ out_attn){
    extern __shared__ float sm[];
    float* BvS = sm + FK_BV;                       // [j=128][k=128] pitch 132
    float* A8  = sm + FK_A8;                       // [8][128]
    int b = blockIdx.y, ic = blockIdx.x, tid = threadIdx.x;
    int j = tid & 127, half = tid >> 7;

    // attn-weight reduce: slice f in [ic*4, ic*4+4)
    {
        int o = tid;
        #pragma unroll
        for (int rep = 0; rep < 4; rep++, o += 256){
            int f = ic*4 + (o >> 8), m = o & 255;
            const float* src = g_pw + ((size_t)b*16)*cTf*cTm + f*cTm + m;
            float s = 0.f;
            #pragma unroll
            for (int g16 = 0; g16 < 16; g16++) s += src[(size_t)g16*cTf*cTm];
            out_attn[((size_t)b*cTf + f)*cTm + m] = s * (1.f/128.f);
        }
    }

    for (int r = half; r < cN; r += 2)
        BvS[r*132 + j] = g_Bv[((size_t)b*cN + r)*cH + j];
    #pragma unroll
    for (int ii = 0; ii < 4; ii++)
        A8[(half*4 + ii)*128 + j] = g_A[((size_t)b*cN + ic*8 + half*4 + ii)*cH + j];
    if (half == 0){
        sm[FK_WA + j] = W1[(2*cE)*cH + j];
        sm[FK_WG + j] = W1[(2*cE + 1)*cH + j];
        sm[FK_W2 + j] = W2[j];
    }
    float b2v = b2[0];
    __syncthreads();

    const float4* brow4 = (const float4*)(BvS + j*132);
    const float4* Wa4 = (const float4*)(sm + FK_WA);
    const float4* Wg4 = (const float4*)(sm + FK_WG);
    const float4* W24 = (const float4*)(sm + FK_W2);
    const float4* arow4_0 = (const float4*)(A8 + (half*4 + 0)*128);
    const float4* arow4_1 = (const float4*)(A8 + (half*4 + 1)*128);
    const float4* arow4_2 = (const float4*)(A8 + (half*4 + 2)*128);
    const float4* arow4_3 = (const float4*)(A8 + (half*4 + 3)*128);

    float adjv[4], gv[4];
    size_t rb0 = ((size_t)b*cN + ic*8 + half*4)*cN + j;
    #pragma unroll
    for (int ii = 0; ii < 4; ii++){
        adjv[ii] = adj[rb0 + (size_t)ii*cN];
        gv[ii]   = gpre[rb0 + (size_t)ii*cN];
    }

    float acc[4] = {0.f, 0.f, 0.f, 0.f};
    #pragma unroll 8
    for (int k4 = 0; k4 < 32; k4++){
        float4 wa = Wa4[k4], wg = Wg4[k4], w2 = W24[k4], v4 = brow4[k4];
        #pragma unroll
        for (int ii = 0; ii < 4; ii++){
            float4 a4 = (ii == 0) ? arow4_0[k4] : (ii == 1) ? arow4_1[k4]
                       : (ii == 2) ? arow4_2[k4] : arow4_3[k4];
            float p0 = fmaf(adjv[ii], wa.x, a4.x + v4.x); p0 = fmaf(gv[ii], wg.x, p0);
            float p1 = fmaf(adjv[ii], wa.y, a4.y + v4.y); p1 = fmaf(gv[ii], wg.y, p1);
            float p2 = fmaf(adjv[ii], wa.z, a4.z + v4.z); p2 = fmaf(gv[ii], wg.z, p2);
            float p3 = fmaf(adjv[ii], wa.w, a4.w + v4.w); p3 = fmaf(gv[ii], wg.w, p3);
            float s = acc[ii];
            s = fmaf(fmaxf(p0, 0.f), w2.x, s);
            s = fmaf(fmaxf(p1, 0.f), w2.y, s);
            s = fmaf(fmaxf(p2, 0.f), w2.z, s);
            s = fmaf(fmaxf(p3, 0.f), w2.w, s);
            acc[ii] = s;
        }
    }
    #pragma unroll
    for (int ii = 0; ii < 4; ii++)
        out[rb0 + (size_t)ii*cN] = acc[ii] + b2v;
}

// ---------------- launch ----------------
extern "C" void kernel_launch(void* const* d_in, const int* in_sizes, int n_in,
                              void* d_out, int out_size){
    const float* noisy_adj  = (const float*)d_in[0];
    const float* node_feats = (const float*)d_in[1];
    const float* feat_fnirs = (const float*)d_in[2];
    const float* feat_music = (const float*)d_in[3];
    const float* g_pre      = (const float*)d_in[4];
    const float* node_W     = (const float*)d_in[5];
    const float* node_b     = (const float*)d_in[6];
    const float* fnirs_W    = (const float*)d_in[7];
    const float* fnirs_b    = (const float*)d_in[8];
    const float* music_W    = (const float*)d_in[9];
    const float* music_b    = (const float*)d_in[10];
    const float* mlp_W1     = (const float*)d_in[11];
    const float* mlp_b1     = (const float*)d_in[12];
    const float* mlp_W2     = (const float*)d_in[13];
    const float* mlp_b2     = (const float*)d_in[14];
    const int*   t          = (const int*)d_in[15];

    float* out      = (float*)d_out;
    float* out_attn = out + cB*cN*cN;
    float* out_loss = out + cB*cN*cN + cB*cTf*cTm;

    cudaFuncSetAttribute(prep_kernel,  cudaFuncAttributeMaxDynamicSharedMemorySize, 139776);
    cudaFuncSetAttribute(attn_kernel,  cudaFuncAttributeMaxDynamicSharedMemorySize, ATTN_SMEM);
    cudaFuncSetAttribute(final_kernel, cudaFuncAttributeMaxDynamicSharedMemorySize, FK_SMEM);

    prep_kernel<<<640, 256, 139776>>>(feat_music, music_W, music_b,
                                      node_feats, node_W, node_b,
                                      feat_fnirs, fnirs_W, fnirs_b, t, out_loss);
    attn_kernel<<<cB*16, 256, ATTN_SMEM>>>(t, mlp_W1, mlp_b1, out_loss);
    final_kernel<<<dim3(16, cB), 256, FK_SMEM>>>(noisy_adj, g_pre, mlp_W1, mlp_W2, mlp_b2,
                                                 out, out_attn);
}

// round 17
// speedup vs baseline: 1.0506x; 1.0506x over previous
#include <cuda_runtime.h>
#include <cuda_bf16.h>
#include <math.h>
#include <stdint.h>

#define cB 8
#define cN 128
#define cF 128
#define cTf 64
#define cTm 256
#define cDf 32
#define cDm 128
#define cE 64
#define cH 128
#define QSCALE 0.08838834764831843f

typedef unsigned long long ull;

// ---------------- device scratch ----------------
__device__ __align__(16) unsigned char g_kvB[cB*65536];     // per b: swizzled [m=256][h=128] bf16
__device__ __align__(16) unsigned char g_qA[cB*cN*16384];   // per n: swizzled [f=64][h=128] bf16 (q*scale)
__device__ float g_qt[cB*cN*cH];                            // q at t-row (fp32)
__device__ float g_h[cB*cN*cE];                             // node hidden
__device__ float g_A[cB*cN*cH];
__device__ float g_Bv[cB*cN*cH];
__device__ float g_pw[cB*16*cTf*cTm];                       // attn-weight partials per n-group

// ---------------- helpers ----------------
__device__ __forceinline__ uint32_t smem_u32(const void* p){
    uint32_t a;
    asm("{ .reg .u64 t; cvta.to.shared.u64 t, %1; cvt.u32.u64 %0, t; }" : "=r"(a) : "l"(p));
    return a;
}
__device__ __forceinline__ uint32_t tile_off(int r, int c, int atom_rows){
    uint32_t boff = (uint32_t)((r>>3) + (c>>6)*atom_rows)*1024u + (uint32_t)(r&7)*128u + (uint32_t)(c&63)*2u;
    return boff ^ ((boff >> 3) & 0x70u);
}
#define LDM_X4(r, a) \
    asm volatile("ldmatrix.sync.aligned.m8n8.x4.shared.b16 {%0,%1,%2,%3}, [%4];" \
        : "=r"((r)[0]),"=r"((r)[1]),"=r"((r)[2]),"=r"((r)[3]) : "r"(a))

__device__ __forceinline__ void mma_bf16(float* c, const uint32_t* a, uint32_t b0, uint32_t b1){
    asm volatile("mma.sync.aligned.m16n8k16.row.col.f32.bf16.bf16.f32 "
        "{%0,%1,%2,%3}, {%4,%5,%6,%7}, {%8,%9}, {%0,%1,%2,%3};"
        : "+f"(c[0]),"+f"(c[1]),"+f"(c[2]),"+f"(c[3])
        : "r"(a[0]),"r"(a[1]),"r"(a[2]),"r"(a[3]), "r"(b0),"r"(b1));
}

// fast exp on the FMA pipe
__device__ __forceinline__ float fexp(float v){
    float t = fmaf(v, 1.4426950408889634f, 12582912.0f);
    int   j = __float_as_int(t) - 0x4B400000;
    float kf = t - 12582912.0f;
    float x = fmaf(kf, -0.6931471805599453f, v);
    float p = 1.3888889e-3f;
    p = fmaf(p, x, 8.3333333e-3f);
    p = fmaf(p, x, 4.1666667e-2f);
    p = fmaf(p, x, 1.6666667e-1f);
    p = fmaf(p, x, 0.5f);
    p = fmaf(p, x, 1.0f);
    p = fmaf(p, x, 1.0f);
    return p * __int_as_float((j + 127) << 23);
}

// packed f32x2
__device__ __forceinline__ ull pack2(float x){ ull r; asm("mov.b64 %0, {%1, %1};" : "=l"(r) : "f"(x)); return r; }
__device__ __forceinline__ ull packab(float a, float b){ ull r; asm("mov.b64 %0, {%1, %2};" : "=l"(r) : "f"(a), "f"(b)); return r; }
__device__ __forceinline__ void fma2(ull &acc, ull a, ull b){ asm("fma.rn.f32x2 %0, %1, %2, %0;" : "+l"(acc) : "l"(a), "l"(b)); }
__device__ __forceinline__ float2 u2f2(ull v){ float2 f; asm("mov.b64 {%0, %1}, %2;" : "=f"(f.x), "=f"(f.y) : "l"(v)); return f; }

// ---------------- kv (blocks 0..63) + node-h (blocks 64..127) ----------------
__global__ void __launch_bounds__(256) kvh_kernel(const float* __restrict__ music,
                                                  const float* __restrict__ W,
                                                  const float* __restrict__ bias,
                                                  const float* __restrict__ nf,
                                                  const float* __restrict__ Wn,
                                                  const float* __restrict__ bn){
    extern __shared__ float sm[];
    int tid = threadIdx.x;
    if (blockIdx.x < 64){
        float* sW = sm + 128*257;
        int b = blockIdx.x >> 3, hc = blockIdx.x & 7;
        for (int idx = tid; idx < cTm*cDm; idx += 256){
            int m = idx >> 7, d = idx & 127;
            sm[d*257 + m] = music[((size_t)b*cTm + m)*cDm + d];
        }
        for (int idx = tid; idx < 128*16; idx += 256){
            int d = idx >> 4, hh = idx & 15;
            sW[idx] = W[d*cH + hc*16 + hh];
        }
        __syncthreads();
        int m = tid;
        unsigned char* tb = g_kvB + (size_t)b*65536;
        for (int hh = 0; hh < 16; hh++){
            int h = hc*16 + hh;
            float acc = bias[h];
            #pragma unroll 8
            for (int d = 0; d < cDm; d++)
                acc = fmaf(sm[d*257 + m], sW[d*16 + hh], acc);
            *(__nv_bfloat16*)(tb + tile_off(m, h, 32)) = __float2bfloat16(acc);
        }
    } else {
        int idx = blockIdx.x - 64;
        int b = idx >> 3, n0 = (idx & 7) * 16;
        float* sWn = sm;             // [f=128][e=64]
        float* sNF = sm + 8192;      // [16 n][128 f]
        {
            const float4* s1 = (const float4*)Wn;
            float4* d1 = (float4*)sWn;
            for (int i = tid; i < 2048; i += 256) d1[i] = s1[i];
            const float4* s2 = (const float4*)(nf + (size_t)(b*cN + n0)*cF);
            float4* d2 = (float4*)sNF;
            for (int i = tid; i < 512; i += 256) d2[i] = s2[i];
        }
        __syncthreads();
        int e = tid & 63, nn = tid >> 6;
        float a0 = bn[e], a1 = a0, a2 = a0, a3 = a0;
        const float* f0 = sNF + (nn*4+0)*cF;
        const float* f1 = sNF + (nn*4+1)*cF;
        const float* f2 = sNF + (nn*4+2)*cF;
        const float* f3 = sNF + (nn*4+3)*cF;
        #pragma unroll 8
        for (int f = 0; f < cF; f++){
            float w = sWn[f*cE + e];
            a0 = fmaf(f0[f], w, a0);
            a1 = fmaf(f1[f], w, a1);
            a2 = fmaf(f2[f], w, a2);
            a3 = fmaf(f3[f], w, a3);
        }
        size_t hb = (size_t)(b*cN + n0 + nn*4)*cE + e;
        g_h[hb]        = a0;
        g_h[hb + cE]   = a1;
        g_h[hb + 2*cE] = a2;
        g_h[hb + 3*cE] = a3;
    }
}

// ---------------- q -> bf16 scaled tile (per n) + t-row fp32 (+ loss zero) ----------------
__global__ void __launch_bounds__(128) qpre_kernel(const float* __restrict__ feat,
                                                   const float* __restrict__ W,
                                                   const float* __restrict__ bias,
                                                   const int* __restrict__ t,
                                                   float* __restrict__ out_loss){
    __shared__ float sfeat[cTf*cDf];
    int bn = blockIdx.x, tid = threadIdx.x;
    int b = bn >> 7;
    if (bn == 0 && tid == 0) *out_loss = 0.f;
    int trow = t[b]; trow = trow < 0 ? 0 : (trow > cTf-1 ? cTf-1 : trow);
    {
        const float4* fs = (const float4*)(feat + (size_t)bn*cTf*cDf);
        float4* fd = (float4*)sfeat;
        #pragma unroll
        for (int i = tid; i < 512; i += 128) fd[i] = fs[i];
    }
    float w[cDf];
    #pragma unroll
    for (int d = 0; d < cDf; d++) w[d] = W[d*cH + tid];
    float bs = bias[tid];
    __syncthreads();
    unsigned char* tb = g_qA + (size_t)bn*16384;
    for (int j = 0; j < 32; j++){
        ull acc = pack2(bs);
        const float* ra = sfeat + (2*j)*cDf;
        const float* rb = sfeat + (2*j+1)*cDf;
        #pragma unroll
        for (int d = 0; d < cDf; d++)
            fma2(acc, packab(ra[d], rb[d]), pack2(w[d]));
        float2 q2 = u2f2(acc);
        if (2*j   == trow) g_qt[(size_t)bn*cH + tid] = q2.x;
        if (2*j+1 == trow) g_qt[(size_t)bn*cH + tid] = q2.y;
        *(__nv_bfloat16*)(tb + tile_off(2*j,   tid, 8)) = __float2bfloat16(q2.x * QSCALE);
        *(__nv_bfloat16*)(tb + tile_off(2*j+1, tid, 8)) = __float2bfloat16(q2.y * QSCALE);
    }
}

// ---------------- attention + fused ab tail ----------------
#define SM_B    0
#define SM_A    65536
#define SM_ZU   98304
#define SM_PROW 102400
#define SM_RED  110592
#define SM_HT   110848
#define SM_TES  112896
#define ATTN_SMEM 113152

__global__ void __launch_bounds__(256, 1) attn_kernel(const int* __restrict__ t,
                                                      const float* __restrict__ W1,
                                                      const float* __restrict__ b1,
                                                      float* __restrict__ out_loss){
    extern __shared__ char smem[];
    uint32_t sbase = smem_u32(smem);
    float2* zu    = (float2*)(smem + SM_ZU);    // [2][64 rows][4 wm] (dead after main loop)
    float*  cT    = (float*)(smem + SM_ZU);     // reuse: [c=128][8n]
    float*  prowS = (float*)(smem + SM_PROW);   // [8 n][256 m]
    float*  red   = (float*)(smem + SM_RED);
    float*  hT    = (float*)(smem + SM_HT);     // [e=64][8n]
    float*  tes   = (float*)(smem + SM_TES);    // 64

    int tid = threadIdx.x, wid = tid >> 5, lane = tid & 31;
    int b = blockIdx.x >> 4, grp = blockIdx.x & 15, nbase = grp * 8;
    int bn0 = b*cN + nbase;
    int wf = wid >> 2, wm = wid & 3;
    int f0 = wf*32, m0 = wm*64;
    int qr = lane >> 2, qc = lane & 3;

    {
        const float4* bs = (const float4*)(g_kvB + (size_t)b*65536);
        float4* bd = (float4*)(smem + SM_B);
        #pragma unroll
        for (int i = 0; i < 16; i++) bd[tid + i*256] = bs[tid + i*256];
        const float4* as = (const float4*)(g_qA + (size_t)bn0*16384);
        float4* ad = (float4*)(smem + SM_A);
        #pragma unroll
        for (int i = 0; i < 4; i++) ad[tid + i*256] = as[tid + i*256];
    }
    __syncthreads();

    int trow = t[b]; trow = trow < 0 ? 0 : (trow > cTf-1 ? cTf-1 : trow);
    float entacc = 0.f;
    float accW[2][8][4];
    #pragma unroll
    for (int mt = 0; mt < 2; mt++)
        #pragma unroll
        for (int nt = 0; nt < 8; nt++)
            #pragma unroll
            for (int i = 0; i < 4; i++) accW[mt][nt][i] = 0.f;

    int arow = (lane & 15), acolk = (lane >> 4) * 8;
    int brow = ((lane >> 4) & 1) * 8 + (lane & 7), bcolk = ((lane >> 3) & 1) * 8;

    for (int np = 0; np < 8; np++){
        uint32_t smA = sbase + SM_A + (np&1)*16384;
        uint32_t smB = sbase + SM_B;

        float C[2][8][4];
        #pragma unroll
        for (int mt = 0; mt < 2; mt++)
            #pragma unroll
            for (int nt = 0; nt < 8; nt++)
                #pragma unroll
                for (int i = 0; i < 4; i++) C[mt][nt][i] = 0.f;

        #pragma unroll
        for (int kk = 0; kk < 8; kk++){
            int k0 = kk*16;
            uint32_t a0[4], a1[4], bb[4][4];
            LDM_X4(a0, smA + tile_off(f0 + arow,      k0 + acolk, 8));
            LDM_X4(a1, smA + tile_off(f0 + 16 + arow, k0 + acolk, 8));
            #pragma unroll
            for (int nt2 = 0; nt2 < 4; nt2++)
                LDM_X4(bb[nt2], smB + tile_off(m0 + nt2*16 + brow, k0 + bcolk, 32));
            #pragma unroll
            for (int nt = 0; nt < 8; nt++){
                uint32_t b0 = bb[nt>>1][(nt&1)*2], b1v = bb[nt>>1][(nt&1)*2 + 1];
                mma_bf16(C[0][nt], a0, b0, b1v);
                mma_bf16(C[1][nt], a1, b0, b1v);
            }
        }

        // early LDG of next A tile
        float4 stg0, stg1, stg2, stg3;
        if (np < 7){
            const float4* as = (const float4*)(g_qA + (size_t)(bn0 + np + 1)*16384);
            stg0 = as[tid];       stg1 = as[tid + 256];
            stg2 = as[tid + 512]; stg3 = as[tid + 768];
        }

        // ---- part1: exp + Z/U + zu write ----
        #pragma unroll
        for (int g = 0; g < 4; g++){
            int mt = g >> 1, pr = g & 1;
            float Z = 0.f, U = 0.f;
            #pragma unroll
            for (int nt = 0; nt < 8; nt++){
                #pragma unroll
                for (int c = 0; c < 2; c++){
                    float v = C[mt][nt][pr*2 + c];
                    float e = fexp(v);
                    Z += e; U = fmaf(e, v, U);
                    C[mt][nt][pr*2 + c] = e;
                }
            }
            #pragma unroll
            for (int o = 1; o <= 2; o <<= 1){
                Z += __shfl_xor_sync(0xffffffffu, Z, o);
                U += __shfl_xor_sync(0xffffffffu, U, o);
            }
            if (qc == 0){
                int f = f0 + mt*16 + qr + 8*pr;
                zu[(np&1)*256 + f*4 + wm] = make_float2(Z, U);
            }
        }

        if (np < 7){
            float4* ad = (float4*)(smem + SM_A + ((np+1)&1)*16384);
            ad[tid]       = stg0; ad[tid + 256] = stg1;
            ad[tid + 512] = stg2; ad[tid + 768] = stg3;
        }
        __syncthreads();

        // ---- part2 ----
        #pragma unroll
        for (int g = 0; g < 4; g++){
            int mt = g >> 1, pr = g & 1;
            int f = f0 + mt*16 + qr + 8*pr;
            const float2* zr = zu + (np&1)*256 + f*4;
            float2 z0 = zr[0], z1 = zr[1], z2 = zr[2], z3 = zr[3];
            float Zt = z0.x + z1.x + z2.x + z3.x;
            float Ut = z0.y + z1.y + z2.y + z3.y;
            float inv = __fdividef(1.f, Zt);
            if (wm == 0 && qc == 0) entacc += __logf(Zt) - Ut*inv;
            bool isT = (f == trow);
            #pragma unroll
            for (int nt = 0; nt < 8; nt++){
                #pragma unroll
                for (int c = 0; c < 2; c++){
                    float p = C[mt][nt][pr*2 + c] * inv;
                    accW[mt][nt][pr*2 + c] += p;
                    if (isT) prowS[np*256 + m0 + nt*8 + 2*qc + c] = p;
                }
            }
        }
    }
    __syncthreads();    // zu dead from here; cT aliases it

    // ctx for the 8 t-rows -> cT[h][8n] = qt + ctx
    {
        int g = tid >> 7, h = tid & 127;
        uint32_t hbase = (uint32_t)(h >> 6)*32768u;
        uint32_t hlow  = (uint32_t)((h & 63)*2);
        uint32_t offj[8];
        #pragma unroll
        for (int j = 0; j < 8; j++) offj[j] = (uint32_t)(j*128) + (hlow ^ (uint32_t)(j<<4));
        float c0=0.f, c1=0.f, c2=0.f, c3=0.f;
        const float* pr = prowS + g*4*256;
        for (int mg = 0; mg < 32; mg++){
            uint32_t abase = hbase + (uint32_t)mg*1024u;
            #pragma unroll
            for (int j = 0; j < 8; j++){
                unsigned short u = *(const unsigned short*)(smem + SM_B + abase + offj[j]);
                float kvv = __bfloat162float(*reinterpret_cast<__nv_bfloat16*>(&u));
                int m = mg*8 + j;
                c0 = fmaf(pr[m],       kvv, c0);
                c1 = fmaf(pr[256 + m], kvv, c1);
                c2 = fmaf(pr[512 + m], kvv, c2);
                c3 = fmaf(pr[768 + m], kvv, c3);
            }
        }
        size_t qb = ((size_t)bn0 + 4*g)*cH + h;
        cT[h*8 + 4*g + 0] = g_qt[qb]        + c0;
        cT[h*8 + 4*g + 1] = g_qt[qb + cH]   + c1;
        cT[h*8 + 4*g + 2] = g_qt[qb + 2*cH] + c2;
        cT[h*8 + 4*g + 3] = g_qt[qb + 3*cH] + c3;
    }

    // stage hT [e][8n], tes
    for (int i = tid; i < 512; i += 256){
        int n = i >> 6, e = i & 63;
        hT[e*8 + n] = g_h[(size_t)(bn0 + n)*cE + e];
    }
    if (tid < 32){
        float invf = expf(-(float)tid * (logf(10000.0f) / 31.0f));
        float fr = (float)trow * invf;
        tes[tid]      = sinf(fr);
        tes[tid + 32] = cosf(fr);
    }

    #pragma unroll
    for (int o = 16; o > 0; o >>= 1) entacc += __shfl_xor_sync(0xffffffffu, entacc, o);
    if (lane == 0) red[wid] = entacc;
    __syncthreads();    // covers cT, hT, tes, red
    if (tid == 0){
        float tot = 0.f;
        #pragma unroll
        for (int i = 0; i < 8; i++) tot += red[i];
        atomicAdd(out_loss, tot * (1.f/(float)(cB*cN*cTf)));
    }

    // attn-weight partials: plain STG.64
    float* pw = g_pw + ((size_t)(b*16 + grp))*cTf*cTm;
    #pragma unroll
    for (int mt = 0; mt < 2; mt++)
        #pragma unroll
        for (int nt = 0; nt < 8; nt++)
            #pragma unroll
            for (int pr = 0; pr < 2; pr++){
                int f = f0 + mt*16 + qr + 8*pr;
                int m = m0 + nt*8 + 2*qc;
                *(float2*)(pw + f*cTm + m) =
                    make_float2(accW[mt][nt][pr*2], accW[mt][nt][pr*2 + 1]);
            }

    // ---- fused ab: thread (k = tid&127, g2 = tid>>7), 4 n each ----
    {
        int k = tid & 127, g2 = tid >> 7;
        float tw = b1[k];
        #pragma unroll 8
        for (int e = 0; e < 64; e++)
            tw = fmaf(tes[e], W1[(258 + e)*cH + k], tw);
        float a[4] = {0.f, 0.f, 0.f, 0.f};
        float bv[4] = {tw, tw, tw, tw};
        const float4* hr = (const float4*)hT + g2;
        const float4* cr = (const float4*)cT + g2;
        #pragma unroll 8
        for (int e = 0; e < 64; e++){
            float wa = W1[e*cH + k];
            float wb = W1[(64 + e)*cH + k];
            float4 h4 = hr[e*2];
            a[0]  = fmaf(h4.x, wa, a[0]);  a[1]  = fmaf(h4.y, wa, a[1]);
            a[2]  = fmaf(h4.z, wa, a[2]);  a[3]  = fmaf(h4.w, wa, a[3]);
            bv[0] = fmaf(h4.x, wb, bv[0]); bv[1] = fmaf(h4.y, wb, bv[1]);
            bv[2] = fmaf(h4.z, wb, bv[2]); bv[3] = fmaf(h4.w, wb, bv[3]);
        }
        #pragma unroll 8
        for (int c = 0; c < 128; c++){
            float wc = W1[(130 + c)*cH + k];
            float4 c4 = cr[c*2];
            bv[0] = fmaf(c4.x, wc, bv[0]); bv[1] = fmaf(c4.y, wc, bv[1]);
            bv[2] = fmaf(c4.z, wc, bv[2]); bv[3] = fmaf(c4.w, wc, bv[3]);
        }
        size_t i0 = (size_t)(bn0 + 4*g2)*cH + k;
        #pragma unroll
        for (int i = 0; i < 4; i++){
            g_A[i0 + (size_t)i*cH]  = a[i];
            g_Bv[i0 + (size_t)i*cH] = bv[i];
        }
    }
}

// ---------------- final edge MLP (k-outer) + attn-weight reduce head ----------------
#define FK_BV   0
#define FK_A8   16896
#define FK_WA   17920
#define FK_WG   18048
#define FK_W2   18176
#define FK_SMEM ((18176 + 128 + 32) * 4)

__global__ void __launch_bounds__(256) final_kernel(const float* __restrict__ adj,
                                                    const float* __restrict__ gpre,
                                                    const float* __restrict__ W1,
                                                    const float* __restrict__ W2,
                                                    const float* __restrict__ b2,
                                                    float* __restrict__ out,
                                                    float* __restrict__ out_attn){
    extern __shared__ float sm[];
    float* BvS = sm + FK_BV;                       // [j=128][k=128] pitch 132
    float* A8  = sm + FK_A8;                       // [8][128]
    int b = blockIdx.y, ic = blockIdx.x, tid = threadIdx.x;
    int j = tid & 127, half = tid >> 7;

    // attn-weight reduce: slice f in [ic*4, ic*4+4)
    {
        int o = tid;
        #pragma unroll
        for (int rep = 0; rep < 4; rep++, o += 256){
            int f = ic*4 + (o >> 8), m = o & 255;
            const float* src = g_pw + ((size_t)b*16)*cTf*cTm + f*cTm + m;
            float s = 0.f;
            #pragma unroll
            for (int g16 = 0; g16 < 16; g16++) s += src[(size_t)g16*cTf*cTm];
            out_attn[((size_t)b*cTf + f)*cTm + m] = s * (1.f/128.f);
        }
    }

    for (int r = half; r < cN; r += 2)
        BvS[r*132 + j] = g_Bv[((size_t)b*cN + r)*cH + j];
    #pragma unroll
    for (int ii = 0; ii < 4; ii++)
        A8[(half*4 + ii)*128 + j] = g_A[((size_t)b*cN + ic*8 + half*4 + ii)*cH + j];
    if (half == 0){
        sm[FK_WA + j] = W1[(2*cE)*cH + j];
        sm[FK_WG + j] = W1[(2*cE + 1)*cH + j];
        sm[FK_W2 + j] = W2[j];
    }
    float b2v = b2[0];
    __syncthreads();

    const float4* brow4 = (const float4*)(BvS + j*132);
    const float4* Wa4 = (const float4*)(sm + FK_WA);
    const float4* Wg4 = (const float4*)(sm + FK_WG);
    const float4* W24 = (const float4*)(sm + FK_W2);
    const float4* arow4_0 = (const float4*)(A8 + (half*4 + 0)*128);
    const float4* arow4_1 = (const float4*)(A8 + (half*4 + 1)*128);
    const float4* arow4_2 = (const float4*)(A8 + (half*4 + 2)*128);
    const float4* arow4_3 = (const float4*)(A8 + (half*4 + 3)*128);

    float adjv[4], gv[4];
    size_t rb0 = ((size_t)b*cN + ic*8 + half*4)*cN + j;
    #pragma unroll
    for (int ii = 0; ii < 4; ii++){
        adjv[ii] = adj[rb0 + (size_t)ii*cN];
        gv[ii]   = gpre[rb0 + (size_t)ii*cN];
    }

    float acc[4] = {0.f, 0.f, 0.f, 0.f};
    #pragma unroll 8
    for (int k4 = 0; k4 < 32; k4++){
        float4 wa = Wa4[k4], wg = Wg4[k4], w2 = W24[k4], v4 = brow4[k4];
        #pragma unroll
        for (int ii = 0; ii < 4; ii++){
            float4 a4 = (ii == 0) ? arow4_0[k4] : (ii == 1) ? arow4_1[k4]
                       : (ii == 2) ? arow4_2[k4] : arow4_3[k4];
            float p0 = fmaf(adjv[ii], wa.x, a4.x + v4.x); p0 = fmaf(gv[ii], wg.x, p0);
            float p1 = fmaf(adjv[ii], wa.y, a4.y + v4.y); p1 = fmaf(gv[ii], wg.y, p1);
            float p2 = fmaf(adjv[ii], wa.z, a4.z + v4.z); p2 = fmaf(gv[ii], wg.z, p2);
            float p3 = fmaf(adjv[ii], wa.w, a4.w + v4.w); p3 = fmaf(gv[ii], wg.w, p3);
            float s = acc[ii];
            s = fmaf(fmaxf(p0, 0.f), w2.x, s);
            s = fmaf(fmaxf(p1, 0.f), w2.y, s);
            s = fmaf(fmaxf(p2, 0.f), w2.z, s);
            s = fmaf(fmaxf(p3, 0.f), w2.w, s);
            acc[ii] = s;
        }
    }
    #pragma unroll
    for (int ii = 0; ii < 4; ii++)
        out[rb0 + (size_t)ii*cN] = acc[ii] + b2v;
}

// ---------------- launch ----------------
extern "C" void kernel_launch(void* const* d_in, const int* in_sizes, int n_in,
                              void* d_out, int out_size){
    const float* noisy_adj  = (const float*)d_in[0];
    const float* node_feats = (const float*)d_in[1];
    const float* feat_fnirs = (const float*)d_in[2];
    const float* feat_music = (const float*)d_in[3];
    const float* g_pre      = (const float*)d_in[4];
    const float* node_W     = (const float*)d_in[5];
    const float* node_b     = (const float*)d_in[6];
    const float* fnirs_W    = (const float*)d_in[7];
    const float* fnirs_b    = (const float*)d_in[8];
    const float* music_W    = (const float*)d_in[9];
    const float* music_b    = (const float*)d_in[10];
    const float* mlp_W1     = (const float*)d_in[11];
    const float* mlp_b1     = (const float*)d_in[12];
    const float* mlp_W2     = (const float*)d_in[13];
    const float* mlp_b2     = (const float*)d_in[14];
    const int*   t          = (const int*)d_in[15];

    float* out      = (float*)d_out;
    float* out_attn = out + cB*cN*cN;
    float* out_loss = out + cB*cN*cN + cB*cTf*cTm;

    cudaFuncSetAttribute(kvh_kernel,   cudaFuncAttributeMaxDynamicSharedMemorySize, 139776);
    cudaFuncSetAttribute(attn_kernel,  cudaFuncAttributeMaxDynamicSharedMemorySize, ATTN_SMEM);
    cudaFuncSetAttribute(final_kernel, cudaFuncAttributeMaxDynamicSharedMemorySize, FK_SMEM);

    kvh_kernel<<<128, 256, 139776>>>(feat_music, music_W, music_b,
                                     node_feats, node_W, node_b);
    qpre_kernel<<<cB*cN, 128>>>(feat_fnirs, fnirs_W, fnirs_b, t, out_loss);
    attn_kernel<<<cB*16, 256, ATTN_SMEM>>>(t, mlp_W1, mlp_b1, out_loss);
    final_kernel<<<dim3(16, cB), 256, FK_SMEM>>>(noisy_adj, g_pre, mlp_W1, mlp_W2, mlp_b2,
                                                 out, out_attn);
}